// round 3
// baseline (speedup 1.0000x reference)
#include <cuda_runtime.h>

#define BB 32
#define TT 1024
#define II 256
#define HH 512
#define OO 1000
#define NBLK 128
#define HC 4
#define RT 256

__device__ float g_xg[(size_t)BB * TT * 4 * HH];
__device__ float g_h1[(size_t)BB * TT * HH];
__device__ float g_h2[(size_t)BB * TT * HH];
__device__ float g_hb[2][HH * BB];
__device__ unsigned g_bar[4];

__device__ __forceinline__ unsigned ld_cg_u32(const unsigned* p) {
    unsigned v;
    asm volatile("ld.global.cg.u32 %0, [%1];" : "=r"(v) : "l"(p) : "memory");
    return v;
}

__device__ __forceinline__ void grid_bar(unsigned* ctr, unsigned target) {
    __threadfence();
    __syncthreads();
    if (threadIdx.x == 0) {
        atomicAdd(ctr, 1u);
        while (ld_cg_u32(ctr) < target) { __nanosleep(32); }
    }
    __syncthreads();
}

__device__ __forceinline__ float sigmoidf_(float x) { return 1.f / (1.f + expf(-x)); }

// C[M,N] = A[M,K] @ W[N,K]^T + b1 (+b2). PERM=1: row m=(b*T+t) written to (t*B+b).
template <int PERM>
__global__ void __launch_bounds__(256)
gemm_kernel(const float* __restrict__ A, const float* __restrict__ W,
            const float* __restrict__ b1, const float* __restrict__ b2,
            float* __restrict__ C, int M, int N, int K)
{
    const int BM = 128, BN = 64, BK = 16;
    __shared__ float sA[BK][BM];
    __shared__ float sB[BK][BN];
    const int tid = threadIdx.x;
    const int m0 = blockIdx.y * BM, n0 = blockIdx.x * BN;
    const int tx = tid & 15, ty = tid >> 4;

    float acc[8][4];
#pragma unroll
    for (int i = 0; i < 8; i++)
#pragma unroll
        for (int j = 0; j < 4; j++) acc[i][j] = 0.f;

    for (int k0 = 0; k0 < K; k0 += BK) {
#pragma unroll
        for (int l = 0; l < 2; l++) {
            int idx = tid + l * 256, r = idx >> 2, q = idx & 3;
            float4 v = *(const float4*)(A + (size_t)(m0 + r) * K + k0 + q * 4);
            sA[q*4+0][r] = v.x; sA[q*4+1][r] = v.y; sA[q*4+2][r] = v.z; sA[q*4+3][r] = v.w;
        }
        {
            int r = tid >> 2, q = tid & 3;
            float4 v = *(const float4*)(W + (size_t)(n0 + r) * K + k0 + q * 4);
            sB[q*4+0][r] = v.x; sB[q*4+1][r] = v.y; sB[q*4+2][r] = v.z; sB[q*4+3][r] = v.w;
        }
        __syncthreads();
#pragma unroll
        for (int kk = 0; kk < BK; kk++) {
            float a[8], bv[4];
#pragma unroll
            for (int i = 0; i < 8; i++) a[i] = sA[kk][ty * 8 + i];
#pragma unroll
            for (int j = 0; j < 4; j++) bv[j] = sB[kk][tx * 4 + j];
#pragma unroll
            for (int i = 0; i < 8; i++)
#pragma unroll
                for (int j = 0; j < 4; j++) acc[i][j] = fmaf(a[i], bv[j], acc[i][j]);
        }
        __syncthreads();
    }
#pragma unroll
    for (int i = 0; i < 8; i++) {
        int m = m0 + ty * 8 + i;
        int orow = PERM ? ((m & (TT - 1)) * BB + (m >> 10)) : m;
#pragma unroll
        for (int j = 0; j < 4; j++) {
            int n = n0 + tx * 4 + j;
            float bias = b1[n];
            if (b2) bias += b2[n];
            C[(size_t)orow * N + n] = acc[i][j] + bias;
        }
    }
}

// ---- persistent LSTM: block owns HC=4 hidden cols (16 gate cols), 8 warps x 2 cols
__global__ void __launch_bounds__(RT, 1)
lstm_kernel(const float* __restrict__ xg, const float* __restrict__ whh,
            float* __restrict__ hseq)
{
    extern __shared__ float sm[];
    float* sh = sm;                   // HH*BB transposed h
    float* sg = sm + HH * BB;         // 16*BB
    float* sc = sg + 16 * BB;         // HC*BB
    const int tid = threadIdx.x, lane = tid & 31, warp = tid >> 5;
    const int j0 = blockIdx.x * HC;
    if (tid < HC * BB) sc[tid] = 0.f;

    const int c0 = warp * 2, c1 = c0 + 1;
    const int n0 = (c0 >> 2) * HH + j0 + (c0 & 3);
    const int n1 = (c1 >> 2) * HH + j0 + (c1 & 3);
    const float4* w0 = (const float4*)(whh + (size_t)n0 * HH);
    const float4* w1 = (const float4*)(whh + (size_t)n1 * HH);

    for (int t = 0; t < TT; t++) {
        if (t > 0) {
            const float4* src = (const float4*)g_hb[t & 1];
            float4* dst = (float4*)sh;
#pragma unroll
            for (int i = 0; i < (HH * BB / 4) / RT; i++)
                dst[tid + i * RT] = __ldcg(src + tid + i * RT);
        }
        __syncthreads();
        float a0 = 0.f, a1 = 0.f;
        if (t > 0) {
#pragma unroll 2
            for (int k4 = 0; k4 < HH / 4; k4++) {
                float4 wa = __ldg(w0 + k4), wb = __ldg(w1 + k4);
                const float* hp = sh + k4 * 4 * BB + lane;
                float h0 = hp[0], h1 = hp[BB], h2 = hp[2*BB], h3 = hp[3*BB];
                a0 = fmaf(h0,wa.x,a0); a0 = fmaf(h1,wa.y,a0); a0 = fmaf(h2,wa.z,a0); a0 = fmaf(h3,wa.w,a0);
                a1 = fmaf(h0,wb.x,a1); a1 = fmaf(h1,wb.y,a1); a1 = fmaf(h2,wb.z,a1); a1 = fmaf(h3,wb.w,a1);
            }
        }
        sg[c0 * BB + lane] = a0;
        sg[c1 * BB + lane] = a1;
        __syncthreads();
        if (tid < HC * BB) {
            const int jl = tid >> 5, b = tid & 31, j = j0 + jl;
            const size_t row = (size_t)(t * BB + b) * (4 * HH);
            float gi = xg[row + j]        + sg[(0*HC+jl)*BB + b];
            float gf = xg[row + HH + j]   + sg[(1*HC+jl)*BB + b];
            float gc = xg[row + 2*HH + j] + sg[(2*HC+jl)*BB + b];
            float go = xg[row + 3*HH + j] + sg[(3*HC+jl)*BB + b];
            float iv = sigmoidf_(gi), fv = sigmoidf_(gf);
            float gv = tanhf(gc), ov = sigmoidf_(go);
            float c = fmaf(fv, sc[tid], iv * gv);
            sc[tid] = c;
            float hv = ov * tanhf(c);
            __stcg(&g_hb[(t + 1) & 1][j * BB + b], hv);
            hseq[(size_t)(t * BB + b) * HH + j] = hv;
        }
        if (t < TT - 1) grid_bar(&g_bar[0], (unsigned)((t + 1) * NBLK));
    }
}

// ---- persistent GRU: 12 gate cols, warps 0..5
__global__ void __launch_bounds__(RT, 1)
gru_kernel(const float* __restrict__ xg, const float* __restrict__ whh,
           const float* __restrict__ bhh, float* __restrict__ hseq)
{
    extern __shared__ float sm[];
    float* sh = sm;
    float* sg = sm + HH * BB;
    const int tid = threadIdx.x, lane = tid & 31, warp = tid >> 5;
    const int j0 = blockIdx.x * HC;
    const int c0 = warp * 2, c1 = c0 + 1;
    const bool act = (c1 < 3 * HC);
    const int n0 = (c0 >> 2) * HH + j0 + (c0 & 3);
    const int n1 = (c1 >> 2) * HH + j0 + (c1 & 3);
    const float4* w0 = (const float4*)(whh + (size_t)n0 * HH);
    const float4* w1 = (const float4*)(whh + (size_t)n1 * HH);

    for (int t = 0; t < TT; t++) {
        if (t > 0) {
            const float4* src = (const float4*)g_hb[t & 1];
            float4* dst = (float4*)sh;
#pragma unroll
            for (int i = 0; i < (HH * BB / 4) / RT; i++)
                dst[tid + i * RT] = __ldcg(src + tid + i * RT);
        }
        __syncthreads();
        if (act) {
            float a0 = 0.f, a1 = 0.f;
            if (t > 0) {
#pragma unroll 2
                for (int k4 = 0; k4 < HH / 4; k4++) {
                    float4 wa = __ldg(w0 + k4), wb = __ldg(w1 + k4);
                    const float* hp = sh + k4 * 4 * BB + lane;
                    float h0 = hp[0], h1 = hp[BB], h2 = hp[2*BB], h3 = hp[3*BB];
                    a0 = fmaf(h0,wa.x,a0); a0 = fmaf(h1,wa.y,a0); a0 = fmaf(h2,wa.z,a0); a0 = fmaf(h3,wa.w,a0);
                    a1 = fmaf(h0,wb.x,a1); a1 = fmaf(h1,wb.y,a1); a1 = fmaf(h2,wb.z,a1); a1 = fmaf(h3,wb.w,a1);
                }
            }
            sg[c0 * BB + lane] = a0;
            sg[c1 * BB + lane] = a1;
        }
        __syncthreads();
        if (tid < HC * BB) {
            const int jl = tid >> 5, b = tid & 31, j = j0 + jl;
            const size_t row = (size_t)(t * BB + b) * (3 * HH);
            float hr = sg[(0*HC+jl)*BB + b] + bhh[j];
            float hz = sg[(1*HC+jl)*BB + b] + bhh[HH + j];
            float hn = sg[(2*HC+jl)*BB + b] + bhh[2*HH + j];
            float r = sigmoidf_(xg[row + j] + hr);
            float z = sigmoidf_(xg[row + HH + j] + hz);
            float n = tanhf(fmaf(r, hn, xg[row + 2*HH + j]));
            float hprev = (t > 0) ? sh[j * BB + b] : 0.f;
            float hv = fmaf(z, hprev, (1.f - z) * n);
            __stcg(&g_hb[(t + 1) & 1][j * BB + b], hv);
            hseq[(size_t)(t * BB + b) * HH + j] = hv;
        }
        if (t < TT - 1) grid_bar(&g_bar[1], (unsigned)((t + 1) * NBLK));
    }
}

// ---- persistent RNN-tanh: 4 cols, warps 0,1
__global__ void __launch_bounds__(RT, 1)
rnn_kernel(const float* __restrict__ xg, const float* __restrict__ whh)
{
    extern __shared__ float sm[];
    float* sh = sm;
    float* sg = sm + HH * BB;
    const int tid = threadIdx.x, lane = tid & 31, warp = tid >> 5;
    const int j0 = blockIdx.x * HC;
    const int c0 = warp * 2, c1 = c0 + 1;
    const bool act = (c1 < HC);
    const float4* w0 = (const float4*)(whh + (size_t)(j0 + c0) * HH);
    const float4* w1 = (const float4*)(whh + (size_t)(j0 + c1) * HH);

    for (int t = 0; t < TT; t++) {
        if (t > 0) {
            const float4* src = (const float4*)g_hb[t & 1];
            float4* dst = (float4*)sh;
#pragma unroll
            for (int i = 0; i < (HH * BB / 4) / RT; i++)
                dst[tid + i * RT] = __ldcg(src + tid + i * RT);
        }
        __syncthreads();
        if (act) {
            float a0 = 0.f, a1 = 0.f;
            if (t > 0) {
#pragma unroll 2
                for (int k4 = 0; k4 < HH / 4; k4++) {
                    float4 wa = __ldg(w0 + k4), wb = __ldg(w1 + k4);
                    const float* hp = sh + k4 * 4 * BB + lane;
                    float h0 = hp[0], h1 = hp[BB], h2 = hp[2*BB], h3 = hp[3*BB];
                    a0 = fmaf(h0,wa.x,a0); a0 = fmaf(h1,wa.y,a0); a0 = fmaf(h2,wa.z,a0); a0 = fmaf(h3,wa.w,a0);
                    a1 = fmaf(h0,wb.x,a1); a1 = fmaf(h1,wb.y,a1); a1 = fmaf(h2,wb.z,a1); a1 = fmaf(h3,wb.w,a1);
                }
            }
            sg[c0 * BB + lane] = a0;
            sg[c1 * BB + lane] = a1;
        }
        __syncthreads();
        if (tid < HC * BB) {
            const int jl = tid >> 5, b = tid & 31, j = j0 + jl;
            float hv = tanhf(xg[(size_t)(t * BB + b) * HH + j] + sg[jl * BB + b]);
            __stcg(&g_hb[(t + 1) & 1][j * BB + b], hv);
        }
        if (t < TT - 1) grid_bar(&g_bar[2], (unsigned)((t + 1) * NBLK));
    }
}

__global__ void __launch_bounds__(128)
ln_kernel(float* __restrict__ x, const float* __restrict__ g, const float* __restrict__ b)
{
    __shared__ float red[4];
    const size_t base = (size_t)blockIdx.x * HH;
    const int tid = threadIdx.x;
    float4 v = *(float4*)(x + base + tid * 4);
    float s = v.x + v.y + v.z + v.w;
#pragma unroll
    for (int o = 16; o; o >>= 1) s += __shfl_xor_sync(0xffffffffu, s, o);
    if ((tid & 31) == 0) red[tid >> 5] = s;
    __syncthreads();
    float mu = (red[0] + red[1] + red[2] + red[3]) * (1.f / HH);
    float dx = v.x - mu, dy = v.y - mu, dz = v.z - mu, dw = v.w - mu;
    float q = dx*dx + dy*dy + dz*dz + dw*dw;
#pragma unroll
    for (int o = 16; o; o >>= 1) q += __shfl_xor_sync(0xffffffffu, q, o);
    __syncthreads();
    if ((tid & 31) == 0) red[tid >> 5] = q;
    __syncthreads();
    float rs = rsqrtf((red[0] + red[1] + red[2] + red[3]) * (1.f / HH) + 1e-5f);
    int c = tid * 4;
    float4 o4;
    o4.x = fmaf(dx * rs, g[c+0], b[c+0]);
    o4.y = fmaf(dy * rs, g[c+1], b[c+1]);
    o4.z = fmaf(dz * rs, g[c+2], b[c+2]);
    o4.w = fmaf(dw * rs, g[c+3], b[c+3]);
    *(float4*)(x + base + tid * 4) = o4;
}

__global__ void __launch_bounds__(256)
fc_kernel(const float* __restrict__ w, const float* __restrict__ bias, float* __restrict__ out)
{
    const float* hb = g_hb[0];          // final h (t=TT ⇒ parity 0), layout [k][b]
    const int b = blockIdx.y;
    const int o = blockIdx.x * 8 + (threadIdx.x >> 5);
    const int lane = threadIdx.x & 31;
    float acc = 0.f;
    const float* wr = w + (size_t)o * HH;
#pragma unroll 4
    for (int k = lane; k < HH; k += 32)
        acc = fmaf(hb[k * BB + b], wr[k], acc);
#pragma unroll
    for (int off = 16; off; off >>= 1) acc += __shfl_xor_sync(0xffffffffu, acc, off);
    if (lane == 0) out[b * OO + o] = acc + bias[o];
}

__global__ void reset_kernel() { g_bar[0] = 0; g_bar[1] = 0; g_bar[2] = 0; g_bar[3] = 0; }

extern "C" void kernel_launch(void* const* d_in, const int* in_sizes, int n_in,
                              void* d_out, int out_size)
{
    (void)in_sizes; (void)n_in; (void)out_size;
    const float* x     = (const float*)d_in[0];
    const float* lw_ih = (const float*)d_in[1];
    const float* lw_hh = (const float*)d_in[2];
    const float* lb_ih = (const float*)d_in[3];
    const float* lb_hh = (const float*)d_in[4];
    const float* l1g   = (const float*)d_in[5];
    const float* l1b   = (const float*)d_in[6];
    const float* gw_ih = (const float*)d_in[7];
    const float* gw_hh = (const float*)d_in[8];
    const float* gb_ih = (const float*)d_in[9];
    const float* gb_hh = (const float*)d_in[10];
    const float* l2g   = (const float*)d_in[11];
    const float* l2b   = (const float*)d_in[12];
    const float* rw_ih = (const float*)d_in[13];
    const float* rw_hh = (const float*)d_in[14];
    const float* rb_ih = (const float*)d_in[15];
    const float* rb_hh = (const float*)d_in[16];
    const float* fc_w  = (const float*)d_in[17];
    const float* fc_b  = (const float*)d_in[18];
    float* out = (float*)d_out;

    float *xg, *h1, *h2;
    cudaGetSymbolAddress((void**)&xg, g_xg);
    cudaGetSymbolAddress((void**)&h1, g_h1);
    cudaGetSymbolAddress((void**)&h2, g_h2);

    const int smem = (HH * BB + 16 * BB + HC * BB) * 4;  // 68.6 KB
    static int configured = 0;
    if (!configured) {
        cudaFuncSetAttribute(lstm_kernel, cudaFuncAttributeMaxDynamicSharedMemorySize, smem);
        cudaFuncSetAttribute(gru_kernel,  cudaFuncAttributeMaxDynamicSharedMemorySize, smem);
        cudaFuncSetAttribute(rnn_kernel,  cudaFuncAttributeMaxDynamicSharedMemorySize, smem);
        configured = 1;
    }

    reset_kernel<<<1, 32>>>();

    const int M = BB * TT;
    // LSTM input projection: [M,2048] = x[M,256] @ lw_ih^T, output permuted to [t][b]
    gemm_kernel<1><<<dim3(4 * HH / 64, M / 128), 256>>>(x, lw_ih, lb_ih, lb_hh, xg, M, 4 * HH, II);
    lstm_kernel<<<NBLK, RT, smem>>>(xg, lw_hh, h1);
    ln_kernel<<<M, 128>>>(h1, l1g, l1b);

    gemm_kernel<0><<<dim3(3 * HH / 64, M / 128), 256>>>(h1, gw_ih, gb_ih, nullptr, xg, M, 3 * HH, HH);
    gru_kernel<<<NBLK, RT, smem>>>(xg, gw_hh, gb_hh, h2);
    ln_kernel<<<M, 128>>>(h2, l2g, l2b);

    gemm_kernel<0><<<dim3(HH / 64, M / 128), 256>>>(h2, rw_ih, rb_ih, rb_hh, xg, M, HH, HH);
    rnn_kernel<<<NBLK, RT, smem>>>(xg, rw_hh);

    fc_kernel<<<dim3(OO / 8, BB), 256>>>(fc_w, fc_b, out);
}

// round 4
// speedup vs baseline: 1.2850x; 1.2850x over previous
#include <cuda_runtime.h>

#define BB 32
#define TT 1024
#define II 256
#define HH 512
#define OO 1000
#define NBLK 128
#define RT 256

__device__ float g_xg[(size_t)BB * TT * 4 * HH];   // gate pre-acts, layout [t][n][b]
__device__ float g_h1[(size_t)BB * TT * HH];       // [t*32+b][512]
__device__ float g_h2[(size_t)BB * TT * HH];
__device__ float g_hb[2][HH * BB];                 // h double buffer, [k][b]
__device__ unsigned g_ctr[12];                     // 3 layers x 4 chunks, monotonic

__device__ __forceinline__ unsigned ld_acq(const unsigned* p) {
    unsigned v;
    asm volatile("ld.acquire.gpu.global.u32 %0, [%1];" : "=r"(v) : "l"(p) : "memory");
    return v;
}
__device__ __forceinline__ void red_rel(unsigned* p) {
    asm volatile("red.release.gpu.global.add.u32 [%0], 1;" :: "l"(p) : "memory");
}
__device__ __forceinline__ float sig_(float x) {
    return __fdividef(1.f, 1.f + __expf(-x));
}
__device__ __forceinline__ float tanh_(float x) {
    return 1.f - __fdividef(2.f, __expf(2.f * x) + 1.f);
}

// ---------------- GEMM: C[t][n][b] = A @ W^T + bias ----------------
// PERM=1: A rows m = b*1024 + t (LSTM input x). PERM=2: A rows m = t*32 + b.
// Tile covers 4 t-values x 32 b. Output layout ((t*N + n)*32 + b).
template <int PERM>
__global__ void __launch_bounds__(256)
gemm_kernel(const float* __restrict__ A, const float* __restrict__ W,
            const float* __restrict__ b1, const float* __restrict__ b2,
            float* __restrict__ C, int M, int N, int K)
{
    const int BM = 128, BN = 64, BK = 16;
    __shared__ float sA[BK][BM];
    __shared__ float sB[BK][BN];
    const int tid = threadIdx.x;
    const int n0 = blockIdx.x * BN;
    const int tx = tid & 15, ty = tid >> 4;

    float acc[8][4];
#pragma unroll
    for (int i = 0; i < 8; i++)
#pragma unroll
        for (int j = 0; j < 4; j++) acc[i][j] = 0.f;

    for (int k0 = 0; k0 < K; k0 += BK) {
#pragma unroll
        for (int l = 0; l < 2; l++) {
            int idx = tid + l * 256, r = idx >> 2, q = idx & 3;
            int rowA;
            if (PERM == 1) rowA = (r & 31) * TT + blockIdx.y * 4 + (r >> 5);
            else           rowA = blockIdx.y * 128 + r;
            float4 v = *(const float4*)(A + (size_t)rowA * K + k0 + q * 4);
            sA[q*4+0][r] = v.x; sA[q*4+1][r] = v.y; sA[q*4+2][r] = v.z; sA[q*4+3][r] = v.w;
        }
        {
            int r = tid >> 2, q = tid & 3;
            float4 v = *(const float4*)(W + (size_t)(n0 + r) * K + k0 + q * 4);
            sB[q*4+0][r] = v.x; sB[q*4+1][r] = v.y; sB[q*4+2][r] = v.z; sB[q*4+3][r] = v.w;
        }
        __syncthreads();
#pragma unroll
        for (int kk = 0; kk < BK; kk++) {
            float4 aA = *(const float4*)&sA[kk][ty * 8];
            float4 aB = *(const float4*)&sA[kk][ty * 8 + 4];
            float4 bv = *(const float4*)&sB[kk][tx * 4];
            float a[8] = {aA.x, aA.y, aA.z, aA.w, aB.x, aB.y, aB.z, aB.w};
            float bb[4] = {bv.x, bv.y, bv.z, bv.w};
#pragma unroll
            for (int i = 0; i < 8; i++)
#pragma unroll
                for (int j = 0; j < 4; j++) acc[i][j] = fmaf(a[i], bb[j], acc[i][j]);
        }
        __syncthreads();
    }

    const int r0 = ty * 8;
    const int tglob = blockIdx.y * 4 + (r0 >> 5);
    const int b0 = r0 & 31;
#pragma unroll
    for (int j = 0; j < 4; j++) {
        int n = n0 + tx * 4 + j;
        float bias = b1[n];
        if (b2) bias += b2[n];
        float4 v0 = {acc[0][j] + bias, acc[1][j] + bias, acc[2][j] + bias, acc[3][j] + bias};
        float4 v1 = {acc[4][j] + bias, acc[5][j] + bias, acc[6][j] + bias, acc[7][j] + bias};
        float* cp = C + ((size_t)tglob * N + n) * BB + b0;
        *(float4*)cp = v0;
        *(float4*)(cp + 4) = v1;
    }
}

// ---------------- persistent LSTM ----------------
// 8 warps: cg=w&3 -> 4 gate-cols {4cg..4cg+3} (gate cg, j-offsets 0..3), kh=w>>2 -> k half.
__global__ void __launch_bounds__(RT, 1)
lstm_kernel(const float* __restrict__ xg, const float* __restrict__ whh,
            float* __restrict__ hseq)
{
    extern __shared__ float sm[];
    float* sh = sm;                 // 16384: h(t-1) [k][b]
    float* sg = sm + HH * BB;       // 1024: partials [kh][c][b]
    const int tid = threadIdx.x, lane = tid & 31, w = tid >> 5;
    const int j0 = blockIdx.x * 4;
    const int cg = w & 3, kh = w >> 2;
    unsigned* ctr = &g_ctr[0];
    const unsigned mychunk = blockIdx.x >> 5;

    const float4* wp0 = (const float4*)(whh + ((size_t)cg * HH + j0 + 0) * HH);
    const float4* wp1 = (const float4*)(whh + ((size_t)cg * HH + j0 + 1) * HH);
    const float4* wp2 = (const float4*)(whh + ((size_t)cg * HH + j0 + 2) * HH);
    const float4* wp3 = (const float4*)(whh + ((size_t)cg * HH + j0 + 3) * HH);

    float creg = 0.f;

    for (int t = 0; t < TT; t++) {
        float a0 = 0.f, a1 = 0.f, a2 = 0.f, a3 = 0.f;
        if (t > 0) {
            const float* hb = g_hb[t & 1];
#pragma unroll
            for (int c = 0; c < 4; c++) {
                if (tid == 0) {
                    unsigned tgt = (unsigned)t * 32u;
                    while (ld_acq(ctr + c) < tgt) {}
                }
                __syncthreads();
                {
                    const float4* src = (const float4*)(hb + c * 4096);
                    float4* dst = (float4*)(sh + c * 4096);
#pragma unroll
                    for (int i = 0; i < 4; i++) dst[tid + i * RT] = __ldcg(src + tid + i * RT);
                }
                __syncthreads();
                if ((c >> 1) == kh) {
                    const float* hp0 = sh + c * 4096;
                    const int kb = c * 32;
#pragma unroll 4
                    for (int k4 = 0; k4 < 32; k4++) {
                        float4 w0 = __ldg(wp0 + kb + k4), w1 = __ldg(wp1 + kb + k4);
                        float4 w2 = __ldg(wp2 + kb + k4), w3 = __ldg(wp3 + kb + k4);
                        const float* hp = hp0 + k4 * 128 + lane;
                        float h0 = hp[0], h1 = hp[32], h2 = hp[64], h3 = hp[96];
                        a0 = fmaf(h0,w0.x,a0); a0 = fmaf(h1,w0.y,a0); a0 = fmaf(h2,w0.z,a0); a0 = fmaf(h3,w0.w,a0);
                        a1 = fmaf(h0,w1.x,a1); a1 = fmaf(h1,w1.y,a1); a1 = fmaf(h2,w1.z,a1); a1 = fmaf(h3,w1.w,a1);
                        a2 = fmaf(h0,w2.x,a2); a2 = fmaf(h1,w2.y,a2); a2 = fmaf(h2,w2.z,a2); a2 = fmaf(h3,w2.w,a2);
                        a3 = fmaf(h0,w3.x,a3); a3 = fmaf(h1,w3.y,a3); a3 = fmaf(h2,w3.z,a3); a3 = fmaf(h3,w3.w,a3);
                    }
                }
            }
        }
        const int sgb = (kh * 16 + cg * 4) * BB + lane;
        sg[sgb] = a0; sg[sgb + BB] = a1; sg[sgb + 2*BB] = a2; sg[sgb + 3*BB] = a3;
        __syncthreads();
        if (tid < 128) {
            const int jl = w, b = lane, j = j0 + jl;
            const size_t xb = ((size_t)t * (4*HH) + j0 + jl) * BB + b;
            float gi = xg[xb]             + sg[(     jl)*BB + b] + sg[(16 +      jl)*BB + b];
            float gf = xg[xb +   HH*BB]   + sg[( 4 + jl)*BB + b] + sg[(16 +  4 + jl)*BB + b];
            float gc = xg[xb + 2*HH*BB]   + sg[( 8 + jl)*BB + b] + sg[(16 +  8 + jl)*BB + b];
            float go = xg[xb + 3*HH*BB]   + sg[(12 + jl)*BB + b] + sg[(16 + 12 + jl)*BB + b];
            float iv = sig_(gi), fv = sig_(gf), gv = tanh_(gc), ov = sig_(go);
            creg = fmaf(fv, creg, iv * gv);
            float hv = ov * tanh_(creg);
            __stcg(&g_hb[(t + 1) & 1][j * BB + b], hv);
            hseq[((size_t)t * BB + b) * HH + j] = hv;
        }
        if (t < TT - 1) {
            __syncthreads();
            if (tid == 0) red_rel(ctr + mychunk);
        }
    }
}

// ---------------- persistent GRU ----------------
// 8 warps: cg=w&3 -> 3 cols {3cg..3cg+2}, kh=w>>2.
__global__ void __launch_bounds__(RT, 1)
gru_kernel(const float* __restrict__ xg, const float* __restrict__ whh,
           const float* __restrict__ bhh, float* __restrict__ hseq)
{
    extern __shared__ float sm[];
    float* sh = sm;
    float* sg = sm + HH * BB;       // 768
    const int tid = threadIdx.x, lane = tid & 31, w = tid >> 5;
    const int j0 = blockIdx.x * 4;
    const int cg = w & 3, kh = w >> 2;
    unsigned* ctr = &g_ctr[4];
    const unsigned mychunk = blockIdx.x >> 5;

    const int c0 = 3 * cg, c1 = c0 + 1, c2 = c0 + 2;
    const float4* wp0 = (const float4*)(whh + ((size_t)(c0 >> 2) * HH + j0 + (c0 & 3)) * HH);
    const float4* wp1 = (const float4*)(whh + ((size_t)(c1 >> 2) * HH + j0 + (c1 & 3)) * HH);
    const float4* wp2 = (const float4*)(whh + ((size_t)(c2 >> 2) * HH + j0 + (c2 & 3)) * HH);

    for (int t = 0; t < TT; t++) {
        float a0 = 0.f, a1 = 0.f, a2 = 0.f;
        if (t > 0) {
            const float* hb = g_hb[t & 1];
#pragma unroll
            for (int c = 0; c < 4; c++) {
                if (tid == 0) {
                    unsigned tgt = (unsigned)t * 32u;
                    while (ld_acq(ctr + c) < tgt) {}
                }
                __syncthreads();
                {
                    const float4* src = (const float4*)(hb + c * 4096);
                    float4* dst = (float4*)(sh + c * 4096);
#pragma unroll
                    for (int i = 0; i < 4; i++) dst[tid + i * RT] = __ldcg(src + tid + i * RT);
                }
                __syncthreads();
                if ((c >> 1) == kh) {
                    const float* hp0 = sh + c * 4096;
                    const int kb = c * 32;
#pragma unroll 4
                    for (int k4 = 0; k4 < 32; k4++) {
                        float4 w0 = __ldg(wp0 + kb + k4), w1 = __ldg(wp1 + kb + k4), w2 = __ldg(wp2 + kb + k4);
                        const float* hp = hp0 + k4 * 128 + lane;
                        float h0 = hp[0], h1 = hp[32], h2 = hp[64], h3 = hp[96];
                        a0 = fmaf(h0,w0.x,a0); a0 = fmaf(h1,w0.y,a0); a0 = fmaf(h2,w0.z,a0); a0 = fmaf(h3,w0.w,a0);
                        a1 = fmaf(h0,w1.x,a1); a1 = fmaf(h1,w1.y,a1); a1 = fmaf(h2,w1.z,a1); a1 = fmaf(h3,w1.w,a1);
                        a2 = fmaf(h0,w2.x,a2); a2 = fmaf(h1,w2.y,a2); a2 = fmaf(h2,w2.z,a2); a2 = fmaf(h3,w2.w,a2);
                    }
                }
            }
        }
        const int sgb = (kh * 12 + c0) * BB + lane;
        sg[sgb] = a0; sg[sgb + BB] = a1; sg[sgb + 2*BB] = a2;
        __syncthreads();
        if (tid < 128) {
            const int jl = w, b = lane, j = j0 + jl;
            const size_t xb = ((size_t)t * (3*HH) + j0 + jl) * BB + b;
            float hr = sg[(     jl)*BB + b] + sg[(12 +     jl)*BB + b] + bhh[j];
            float hz = sg[( 4 + jl)*BB + b] + sg[(12 + 4 + jl)*BB + b] + bhh[HH + j];
            float hn = sg[( 8 + jl)*BB + b] + sg[(12 + 8 + jl)*BB + b] + bhh[2*HH + j];
            float r = sig_(xg[xb] + hr);
            float z = sig_(xg[xb + HH*BB] + hz);
            float n = tanh_(fmaf(r, hn, xg[xb + 2*HH*BB]));
            float hprev = (t > 0) ? sh[j * BB + b] : 0.f;
            float hv = fmaf(z, hprev, (1.f - z) * n);
            __stcg(&g_hb[(t + 1) & 1][j * BB + b], hv);
            hseq[((size_t)t * BB + b) * HH + j] = hv;
        }
        if (t < TT - 1) {
            __syncthreads();
            if (tid == 0) red_rel(ctr + mychunk);
        }
    }
}

// ---------------- persistent RNN-tanh ----------------
// 8 warps: col=w&3, kh=w>>2; two accumulators per warp for ILP.
__global__ void __launch_bounds__(RT, 1)
rnn_kernel(const float* __restrict__ xg, const float* __restrict__ whh)
{
    extern __shared__ float sm[];
    float* sh = sm;
    float* sg = sm + HH * BB;       // 256
    const int tid = threadIdx.x, lane = tid & 31, w = tid >> 5;
    const int j0 = blockIdx.x * 4;
    const int col = w & 3, kh = w >> 2;
    unsigned* ctr = &g_ctr[8];
    const unsigned mychunk = blockIdx.x >> 5;
    const float4* wp = (const float4*)(whh + (size_t)(j0 + col) * HH);

    for (int t = 0; t < TT; t++) {
        float a0 = 0.f, a1 = 0.f;
        if (t > 0) {
            const float* hb = g_hb[t & 1];
#pragma unroll
            for (int c = 0; c < 4; c++) {
                if (tid == 0) {
                    unsigned tgt = (unsigned)t * 32u;
                    while (ld_acq(ctr + c) < tgt) {}
                }
                __syncthreads();
                {
                    const float4* src = (const float4*)(hb + c * 4096);
                    float4* dst = (float4*)(sh + c * 4096);
#pragma unroll
                    for (int i = 0; i < 4; i++) dst[tid + i * RT] = __ldcg(src + tid + i * RT);
                }
                __syncthreads();
                if ((c >> 1) == kh) {
                    const float* hp0 = sh + c * 4096;
                    const int kb = c * 32;
#pragma unroll 4
                    for (int k4 = 0; k4 < 32; k4++) {
                        float4 w0 = __ldg(wp + kb + k4);
                        const float* hp = hp0 + k4 * 128 + lane;
                        float h0 = hp[0], h1 = hp[32], h2 = hp[64], h3 = hp[96];
                        if (k4 & 1) {
                            a1 = fmaf(h0,w0.x,a1); a1 = fmaf(h1,w0.y,a1); a1 = fmaf(h2,w0.z,a1); a1 = fmaf(h3,w0.w,a1);
                        } else {
                            a0 = fmaf(h0,w0.x,a0); a0 = fmaf(h1,w0.y,a0); a0 = fmaf(h2,w0.z,a0); a0 = fmaf(h3,w0.w,a0);
                        }
                    }
                }
            }
        }
        sg[(kh * 4 + col) * BB + lane] = a0 + a1;
        __syncthreads();
        if (tid < 128) {
            const int jl = w, b = lane, j = j0 + jl;
            float hv = tanh_(xg[((size_t)t * HH + j0 + jl) * BB + b]
                             + sg[jl * BB + b] + sg[(4 + jl) * BB + b]);
            __stcg(&g_hb[(t + 1) & 1][j * BB + b], hv);
        }
        if (t < TT - 1) {
            __syncthreads();
            if (tid == 0) red_rel(ctr + mychunk);
        }
    }
}

__global__ void __launch_bounds__(128)
ln_kernel(float* __restrict__ x, const float* __restrict__ g, const float* __restrict__ b)
{
    __shared__ float red[4];
    const size_t base = (size_t)blockIdx.x * HH;
    const int tid = threadIdx.x;
    float4 v = *(float4*)(x + base + tid * 4);
    float s = v.x + v.y + v.z + v.w;
#pragma unroll
    for (int o = 16; o; o >>= 1) s += __shfl_xor_sync(0xffffffffu, s, o);
    if ((tid & 31) == 0) red[tid >> 5] = s;
    __syncthreads();
    float mu = (red[0] + red[1] + red[2] + red[3]) * (1.f / HH);
    float dx = v.x - mu, dy = v.y - mu, dz = v.z - mu, dw = v.w - mu;
    float q = dx*dx + dy*dy + dz*dz + dw*dw;
#pragma unroll
    for (int o = 16; o; o >>= 1) q += __shfl_xor_sync(0xffffffffu, q, o);
    __syncthreads();
    if ((tid & 31) == 0) red[tid >> 5] = q;
    __syncthreads();
    float rs = rsqrtf((red[0] + red[1] + red[2] + red[3]) * (1.f / HH) + 1e-5f);
    int c = tid * 4;
    float4 o4;
    o4.x = fmaf(dx * rs, g[c+0], b[c+0]);
    o4.y = fmaf(dy * rs, g[c+1], b[c+1]);
    o4.z = fmaf(dz * rs, g[c+2], b[c+2]);
    o4.w = fmaf(dw * rs, g[c+3], b[c+3]);
    *(float4*)(x + base + tid * 4) = o4;
}

__global__ void __launch_bounds__(256)
fc_kernel(const float* __restrict__ w, const float* __restrict__ bias, float* __restrict__ out)
{
    const float* hb = g_hb[0];
    const int b = blockIdx.y;
    const int o = blockIdx.x * 8 + (threadIdx.x >> 5);
    const int lane = threadIdx.x & 31;
    float acc = 0.f;
    const float* wr = w + (size_t)o * HH;
#pragma unroll 4
    for (int k = lane; k < HH; k += 32)
        acc = fmaf(hb[k * BB + b], wr[k], acc);
#pragma unroll
    for (int off = 16; off; off >>= 1) acc += __shfl_xor_sync(0xffffffffu, acc, off);
    if (lane == 0) out[b * OO + o] = acc + bias[o];
}

__global__ void reset_kernel() {
    if (threadIdx.x < 12) g_ctr[threadIdx.x] = 0;
}

extern "C" void kernel_launch(void* const* d_in, const int* in_sizes, int n_in,
                              void* d_out, int out_size)
{
    (void)in_sizes; (void)n_in; (void)out_size;
    const float* x     = (const float*)d_in[0];
    const float* lw_ih = (const float*)d_in[1];
    const float* lw_hh = (const float*)d_in[2];
    const float* lb_ih = (const float*)d_in[3];
    const float* lb_hh = (const float*)d_in[4];
    const float* l1g   = (const float*)d_in[5];
    const float* l1b   = (const float*)d_in[6];
    const float* gw_ih = (const float*)d_in[7];
    const float* gw_hh = (const float*)d_in[8];
    const float* gb_ih = (const float*)d_in[9];
    const float* gb_hh = (const float*)d_in[10];
    const float* l2g   = (const float*)d_in[11];
    const float* l2b   = (const float*)d_in[12];
    const float* rw_ih = (const float*)d_in[13];
    const float* rw_hh = (const float*)d_in[14];
    const float* rb_ih = (const float*)d_in[15];
    const float* rb_hh = (const float*)d_in[16];
    const float* fc_w  = (const float*)d_in[17];
    const float* fc_b  = (const float*)d_in[18];
    float* out = (float*)d_out;

    float *xg, *h1, *h2;
    cudaGetSymbolAddress((void**)&xg, g_xg);
    cudaGetSymbolAddress((void**)&h1, g_h1);
    cudaGetSymbolAddress((void**)&h2, g_h2);

    const int smem_lstm = (HH * BB + 32 * BB) * 4;
    const int smem_gru  = (HH * BB + 24 * BB) * 4;
    const int smem_rnn  = (HH * BB +  8 * BB) * 4;
    static int configured = 0;
    if (!configured) {
        cudaFuncSetAttribute(lstm_kernel, cudaFuncAttributeMaxDynamicSharedMemorySize, smem_lstm);
        cudaFuncSetAttribute(gru_kernel,  cudaFuncAttributeMaxDynamicSharedMemorySize, smem_gru);
        cudaFuncSetAttribute(rnn_kernel,  cudaFuncAttributeMaxDynamicSharedMemorySize, smem_rnn);
        configured = 1;
    }

    reset_kernel<<<1, 32>>>();

    const int M = BB * TT;
    gemm_kernel<1><<<dim3(4 * HH / 64, M / 128), 256>>>(x, lw_ih, lb_ih, lb_hh, xg, M, 4 * HH, II);
    lstm_kernel<<<NBLK, RT, smem_lstm>>>(xg, lw_hh, h1);
    ln_kernel<<<M, 128>>>(h1, l1g, l1b);

    gemm_kernel<2><<<dim3(3 * HH / 64, M / 128), 256>>>(h1, gw_ih, gb_ih, nullptr, xg, M, 3 * HH, HH);
    gru_kernel<<<NBLK, RT, smem_gru>>>(xg, gw_hh, gb_hh, h2);
    ln_kernel<<<M, 128>>>(h2, l2g, l2b);

    gemm_kernel<2><<<dim3(HH / 64, M / 128), 256>>>(h2, rw_ih, rb_ih, rb_hh, xg, M, HH, HH);
    rnn_kernel<<<NBLK, RT, smem_rnn>>>(xg, rw_hh);

    fc_kernel<<<dim3(OO / 8, BB), 256>>>(fc_w, fc_b, out);
}

// round 5
// speedup vs baseline: 2.1254x; 1.6541x over previous
#include <cuda_runtime.h>

#define BB 32
#define TT 1024
#define II 256
#define HH 512
#define OO 1000
#define NBLK 128
#define RT 256

__device__ float g_xg[(size_t)BB * TT * 4 * HH];   // gate pre-acts, layout [t][n][b]
__device__ float g_h1[(size_t)BB * TT * HH];
__device__ float g_h2[(size_t)BB * TT * HH];
__device__ float g_hb[2][HH * BB];                 // h double buffer, [k][b]
__device__ unsigned g_ctr[12];

__device__ __forceinline__ unsigned ld_acq(const unsigned* p) {
    unsigned v;
    asm volatile("ld.acquire.gpu.global.u32 %0, [%1];" : "=r"(v) : "l"(p) : "memory");
    return v;
}
__device__ __forceinline__ void red_rel(unsigned* p) {
    asm volatile("red.release.gpu.global.add.u32 [%0], 1;" :: "l"(p) : "memory");
}
__device__ __forceinline__ float sig_(float x) {
    return __fdividef(1.f, 1.f + __expf(-x));
}
__device__ __forceinline__ float tanh_(float x) {
    return 1.f - __fdividef(2.f, __expf(2.f * x) + 1.f);
}

// ---------------- GEMM: C[t][n][b] = A @ W^T + bias ----------------
template <int PERM>
__global__ void __launch_bounds__(256)
gemm_kernel(const float* __restrict__ A, const float* __restrict__ W,
            const float* __restrict__ b1, const float* __restrict__ b2,
            float* __restrict__ C, int M, int N, int K)
{
    const int BM = 128, BN = 64, BK = 16;
    __shared__ float sA[BK][BM];
    __shared__ float sB[BK][BN];
    const int tid = threadIdx.x;
    const int n0 = blockIdx.x * BN;
    const int tx = tid & 15, ty = tid >> 4;

    float acc[8][4];
#pragma unroll
    for (int i = 0; i < 8; i++)
#pragma unroll
        for (int j = 0; j < 4; j++) acc[i][j] = 0.f;

    for (int k0 = 0; k0 < K; k0 += BK) {
#pragma unroll
        for (int l = 0; l < 2; l++) {
            int idx = tid + l * 256, r = idx >> 2, q = idx & 3;
            int rowA;
            if (PERM == 1) rowA = (r & 31) * TT + blockIdx.y * 4 + (r >> 5);
            else           rowA = blockIdx.y * 128 + r;
            float4 v = *(const float4*)(A + (size_t)rowA * K + k0 + q * 4);
            sA[q*4+0][r] = v.x; sA[q*4+1][r] = v.y; sA[q*4+2][r] = v.z; sA[q*4+3][r] = v.w;
        }
        {
            int r = tid >> 2, q = tid & 3;
            float4 v = *(const float4*)(W + (size_t)(n0 + r) * K + k0 + q * 4);
            sB[q*4+0][r] = v.x; sB[q*4+1][r] = v.y; sB[q*4+2][r] = v.z; sB[q*4+3][r] = v.w;
        }
        __syncthreads();
#pragma unroll
        for (int kk = 0; kk < BK; kk++) {
            float4 aA = *(const float4*)&sA[kk][ty * 8];
            float4 aB = *(const float4*)&sA[kk][ty * 8 + 4];
            float4 bv = *(const float4*)&sB[kk][tx * 4];
            float a[8] = {aA.x, aA.y, aA.z, aA.w, aB.x, aB.y, aB.z, aB.w};
            float bb[4] = {bv.x, bv.y, bv.z, bv.w};
#pragma unroll
            for (int i = 0; i < 8; i++)
#pragma unroll
                for (int j = 0; j < 4; j++) acc[i][j] = fmaf(a[i], bb[j], acc[i][j]);
        }
        __syncthreads();
    }

    const int r0 = ty * 8;
    const int tglob = blockIdx.y * 4 + (r0 >> 5);
    const int b0 = r0 & 31;
#pragma unroll
    for (int j = 0; j < 4; j++) {
        int n = n0 + tx * 4 + j;
        float bias = b1[n];
        if (b2) bias += b2[n];
        float4 v0 = {acc[0][j] + bias, acc[1][j] + bias, acc[2][j] + bias, acc[3][j] + bias};
        float4 v1 = {acc[4][j] + bias, acc[5][j] + bias, acc[6][j] + bias, acc[7][j] + bias};
        float* cp = C + ((size_t)tglob * N + n) * BB + b0;
        *(float4*)cp = v0;
        *(float4*)(cp + 4) = v1;
    }
}

// ---------------- persistent LSTM ----------------
// 8 warps: cg=w&3 -> gate cg, 4 j-cols; kh=w>>2 -> k half. Weights in SMEM.
__global__ void __launch_bounds__(RT, 1)
lstm_kernel(const float* __restrict__ xg, const float* __restrict__ whh,
            float* __restrict__ hseq)
{
    extern __shared__ float sm[];
    float* sh = sm;                       // 16384 floats: h(t-1) [k][b]
    float* sg = sm + HH * BB;             // 1024: partials
    float4* swf = (float4*)(sg + 32 * BB);// 8 warps x 256 float4 weights
    const int tid = threadIdx.x, lane = tid & 31, w = tid >> 5;
    const int j0 = blockIdx.x * 4;
    const int cg = w & 3, kh = w >> 2;
    unsigned* ctr = &g_ctr[0];
    const unsigned mychunk = blockIdx.x >> 5;

    // preload this warp's weights: [k4l 0..63][colj 0..3] float4
    {
        float4* dst = swf + w * 256;
        const float4* wsrc = (const float4*)whh;
#pragma unroll
        for (int i = 0; i < 8; i++) {
            int j = lane + i * 32;
            int k4l = j >> 2, colj = j & 3;
            dst[k4l * 4 + colj] = __ldg(wsrc + ((size_t)cg * HH + j0 + colj) * 128 + kh * 64 + k4l);
        }
    }
    __syncthreads();

    float creg = 0.f;

    for (int t = 0; t < TT; t++) {
        float a0 = 0.f, a1 = 0.f, a2 = 0.f, a3 = 0.f;
        if (t > 0) {
            const float* hb = g_hb[t & 1];
#pragma unroll
            for (int c = 0; c < 4; c++) {
                if (tid == 0) {
                    unsigned tgt = (unsigned)t * 32u;
                    while (ld_acq(ctr + c) < tgt) {}
                }
                __syncthreads();
                {
                    const float4* src = (const float4*)(hb + c * 4096);
                    float4* dst = (float4*)(sh + c * 4096);
#pragma unroll
                    for (int i = 0; i < 4; i++) dst[tid + i * RT] = __ldcg(src + tid + i * RT);
                }
                __syncthreads();
                if ((c >> 1) == kh) {
                    const float* hp0 = sh + c * 4096;
                    const float4* wb = swf + w * 256 + (c & 1) * 128;
#pragma unroll 4
                    for (int k4 = 0; k4 < 32; k4++) {
                        float4 w0 = wb[k4*4+0], w1 = wb[k4*4+1], w2 = wb[k4*4+2], w3 = wb[k4*4+3];
                        const float* hp = hp0 + k4 * 128 + lane;
                        float h0 = hp[0], h1 = hp[32], h2 = hp[64], h3 = hp[96];
                        a0 = fmaf(h0,w0.x,a0); a0 = fmaf(h1,w0.y,a0); a0 = fmaf(h2,w0.z,a0); a0 = fmaf(h3,w0.w,a0);
                        a1 = fmaf(h0,w1.x,a1); a1 = fmaf(h1,w1.y,a1); a1 = fmaf(h2,w1.z,a1); a1 = fmaf(h3,w1.w,a1);
                        a2 = fmaf(h0,w2.x,a2); a2 = fmaf(h1,w2.y,a2); a2 = fmaf(h2,w2.z,a2); a2 = fmaf(h3,w2.w,a2);
                        a3 = fmaf(h0,w3.x,a3); a3 = fmaf(h1,w3.y,a3); a3 = fmaf(h2,w3.z,a3); a3 = fmaf(h3,w3.w,a3);
                    }
                }
            }
        }
        const int sgb = (kh * 16 + cg * 4) * BB + lane;
        sg[sgb] = a0; sg[sgb + BB] = a1; sg[sgb + 2*BB] = a2; sg[sgb + 3*BB] = a3;
        __syncthreads();
        if (tid < 128) {
            const int jl = w, b = lane, j = j0 + jl;
            const size_t xb = ((size_t)t * (4*HH) + j0 + jl) * BB + b;
            float gi = xg[xb]             + sg[(     jl)*BB + b] + sg[(16 +      jl)*BB + b];
            float gf = xg[xb +   HH*BB]   + sg[( 4 + jl)*BB + b] + sg[(16 +  4 + jl)*BB + b];
            float gc = xg[xb + 2*HH*BB]   + sg[( 8 + jl)*BB + b] + sg[(16 +  8 + jl)*BB + b];
            float go = xg[xb + 3*HH*BB]   + sg[(12 + jl)*BB + b] + sg[(16 + 12 + jl)*BB + b];
            float iv = sig_(gi), fv = sig_(gf), gv = tanh_(gc), ov = sig_(go);
            creg = fmaf(fv, creg, iv * gv);
            float hv = ov * tanh_(creg);
            __stcg(&g_hb[(t + 1) & 1][j * BB + b], hv);
            hseq[((size_t)t * BB + b) * HH + j] = hv;
        }
        if (t < TT - 1) {
            __syncthreads();
            if (tid == 0) red_rel(ctr + mychunk);
        }
    }
}

// ---------------- persistent GRU ----------------
__global__ void __launch_bounds__(RT, 1)
gru_kernel(const float* __restrict__ xg, const float* __restrict__ whh,
           const float* __restrict__ bhh, float* __restrict__ hseq)
{
    extern __shared__ float sm[];
    float* sh = sm;
    float* sg = sm + HH * BB;               // 768
    float4* swf = (float4*)(sg + 24 * BB);   // 8 warps x 256 float4 (slot 3 unused)
    const int tid = threadIdx.x, lane = tid & 31, w = tid >> 5;
    const int j0 = blockIdx.x * 4;
    const int cg = w & 3, kh = w >> 2;
    unsigned* ctr = &g_ctr[4];
    const unsigned mychunk = blockIdx.x >> 5;

    {   // preload: 3 cols x 64 k4l per warp (192 f4), lane loads 6
        float4* dst = swf + w * 256;
        const float4* wsrc = (const float4*)whh;
#pragma unroll
        for (int i = 0; i < 6; i++) {
            int j = lane + i * 32;          // 0..191
            int k4l = j >> 2, colj = j & 3; // colj may be 3 for some j>=... no: use div by 3 mapping
            // remap: iterate cols outer to avoid div: j = colj*64 + k4l
            colj = j / 64; k4l = j % 64;
            int c = 3 * cg + colj;
            dst[k4l * 4 + colj] = __ldg(wsrc + ((size_t)(c >> 2) * HH + j0 + (c & 3)) * 128 + kh * 64 + k4l);
        }
    }
    __syncthreads();

    for (int t = 0; t < TT; t++) {
        float a0 = 0.f, a1 = 0.f, a2 = 0.f;
        if (t > 0) {
            const float* hb = g_hb[t & 1];
#pragma unroll
            for (int c = 0; c < 4; c++) {
                if (tid == 0) {
                    unsigned tgt = (unsigned)t * 32u;
                    while (ld_acq(ctr + c) < tgt) {}
                }
                __syncthreads();
                {
                    const float4* src = (const float4*)(hb + c * 4096);
                    float4* dst = (float4*)(sh + c * 4096);
#pragma unroll
                    for (int i = 0; i < 4; i++) dst[tid + i * RT] = __ldcg(src + tid + i * RT);
                }
                __syncthreads();
                if ((c >> 1) == kh) {
                    const float* hp0 = sh + c * 4096;
                    const float4* wb = swf + w * 256 + (c & 1) * 128;
#pragma unroll 4
                    for (int k4 = 0; k4 < 32; k4++) {
                        float4 w0 = wb[k4*4+0], w1 = wb[k4*4+1], w2 = wb[k4*4+2];
                        const float* hp = hp0 + k4 * 128 + lane;
                        float h0 = hp[0], h1 = hp[32], h2 = hp[64], h3 = hp[96];
                        a0 = fmaf(h0,w0.x,a0); a0 = fmaf(h1,w0.y,a0); a0 = fmaf(h2,w0.z,a0); a0 = fmaf(h3,w0.w,a0);
                        a1 = fmaf(h0,w1.x,a1); a1 = fmaf(h1,w1.y,a1); a1 = fmaf(h2,w1.z,a1); a1 = fmaf(h3,w1.w,a1);
                        a2 = fmaf(h0,w2.x,a2); a2 = fmaf(h1,w2.y,a2); a2 = fmaf(h2,w2.z,a2); a2 = fmaf(h3,w2.w,a2);
                    }
                }
            }
        }
        const int sgb = (kh * 12 + 3 * cg) * BB + lane;
        sg[sgb] = a0; sg[sgb + BB] = a1; sg[sgb + 2*BB] = a2;
        __syncthreads();
        if (tid < 128) {
            const int jl = w, b = lane, j = j0 + jl;
            const size_t xb = ((size_t)t * (3*HH) + j0 + jl) * BB + b;
            float hr = sg[(     jl)*BB + b] + sg[(12 +     jl)*BB + b] + bhh[j];
            float hz = sg[( 4 + jl)*BB + b] + sg[(12 + 4 + jl)*BB + b] + bhh[HH + j];
            float hn = sg[( 8 + jl)*BB + b] + sg[(12 + 8 + jl)*BB + b] + bhh[2*HH + j];
            float r = sig_(xg[xb] + hr);
            float z = sig_(xg[xb + HH*BB] + hz);
            float n = tanh_(fmaf(r, hn, xg[xb + 2*HH*BB]));
            float hprev = (t > 0) ? sh[j * BB + b] : 0.f;
            float hv = fmaf(z, hprev, (1.f - z) * n);
            __stcg(&g_hb[(t + 1) & 1][j * BB + b], hv);
            hseq[((size_t)t * BB + b) * HH + j] = hv;
        }
        if (t < TT - 1) {
            __syncthreads();
            if (tid == 0) red_rel(ctr + mychunk);
        }
    }
}

// ---------------- persistent RNN-tanh ----------------
__global__ void __launch_bounds__(RT, 1)
rnn_kernel(const float* __restrict__ xg, const float* __restrict__ whh)
{
    extern __shared__ float sm[];
    float* sh = sm;
    float* sg = sm + HH * BB;               // 256
    float4* swf = (float4*)(sg + 8 * BB);    // 8 warps x 64 float4
    const int tid = threadIdx.x, lane = tid & 31, w = tid >> 5;
    const int j0 = blockIdx.x * 4;
    const int col = w & 3, kh = w >> 2;
    unsigned* ctr = &g_ctr[8];
    const unsigned mychunk = blockIdx.x >> 5;

    {   // preload: 64 f4 per warp, lane loads 2
        float4* dst = swf + w * 64;
        const float4* wsrc = (const float4*)whh;
#pragma unroll
        for (int i = 0; i < 2; i++) {
            int k4l = lane + i * 32;
            dst[k4l] = __ldg(wsrc + (size_t)(j0 + col) * 128 + kh * 64 + k4l);
        }
    }
    __syncthreads();

    for (int t = 0; t < TT; t++) {
        float a0 = 0.f, a1 = 0.f;
        if (t > 0) {
            const float* hb = g_hb[t & 1];
#pragma unroll
            for (int c = 0; c < 4; c++) {
                if (tid == 0) {
                    unsigned tgt = (unsigned)t * 32u;
                    while (ld_acq(ctr + c) < tgt) {}
                }
                __syncthreads();
                {
                    const float4* src = (const float4*)(hb + c * 4096);
                    float4* dst = (float4*)(sh + c * 4096);
#pragma unroll
                    for (int i = 0; i < 4; i++) dst[tid + i * RT] = __ldcg(src + tid + i * RT);
                }
                __syncthreads();
                if ((c >> 1) == kh) {
                    const float* hp0 = sh + c * 4096;
                    const float4* wb = swf + w * 64 + (c & 1) * 32;
#pragma unroll 4
                    for (int k4 = 0; k4 < 32; k4++) {
                        float4 w0 = wb[k4];
                        const float* hp = hp0 + k4 * 128 + lane;
                        float h0 = hp[0], h1 = hp[32], h2 = hp[64], h3 = hp[96];
                        if (k4 & 1) {
                            a1 = fmaf(h0,w0.x,a1); a1 = fmaf(h1,w0.y,a1); a1 = fmaf(h2,w0.z,a1); a1 = fmaf(h3,w0.w,a1);
                        } else {
                            a0 = fmaf(h0,w0.x,a0); a0 = fmaf(h1,w0.y,a0); a0 = fmaf(h2,w0.z,a0); a0 = fmaf(h3,w0.w,a0);
                        }
                    }
                }
            }
        }
        sg[(kh * 4 + col) * BB + lane] = a0 + a1;
        __syncthreads();
        if (tid < 128) {
            const int jl = w, b = lane, j = j0 + jl;
            float hv = tanh_(xg[((size_t)t * HH + j0 + jl) * BB + b]
                             + sg[jl * BB + b] + sg[(4 + jl) * BB + b]);
            __stcg(&g_hb[(t + 1) & 1][j * BB + b], hv);
        }
        if (t < TT - 1) {
            __syncthreads();
            if (tid == 0) red_rel(ctr + mychunk);
        }
    }
}

__global__ void __launch_bounds__(128)
ln_kernel(float* __restrict__ x, const float* __restrict__ g, const float* __restrict__ b)
{
    __shared__ float red[4];
    const size_t base = (size_t)blockIdx.x * HH;
    const int tid = threadIdx.x;
    float4 v = *(float4*)(x + base + tid * 4);
    float s = v.x + v.y + v.z + v.w;
#pragma unroll
    for (int o = 16; o; o >>= 1) s += __shfl_xor_sync(0xffffffffu, s, o);
    if ((tid & 31) == 0) red[tid >> 5] = s;
    __syncthreads();
    float mu = (red[0] + red[1] + red[2] + red[3]) * (1.f / HH);
    float dx = v.x - mu, dy = v.y - mu, dz = v.z - mu, dw = v.w - mu;
    float q = dx*dx + dy*dy + dz*dz + dw*dw;
#pragma unroll
    for (int o = 16; o; o >>= 1) q += __shfl_xor_sync(0xffffffffu, q, o);
    __syncthreads();
    if ((tid & 31) == 0) red[tid >> 5] = q;
    __syncthreads();
    float rs = rsqrtf((red[0] + red[1] + red[2] + red[3]) * (1.f / HH) + 1e-5f);
    int c = tid * 4;
    float4 o4;
    o4.x = fmaf(dx * rs, g[c+0], b[c+0]);
    o4.y = fmaf(dy * rs, g[c+1], b[c+1]);
    o4.z = fmaf(dz * rs, g[c+2], b[c+2]);
    o4.w = fmaf(dw * rs, g[c+3], b[c+3]);
    *(float4*)(x + base + tid * 4) = o4;
}

__global__ void __launch_bounds__(256)
fc_kernel(const float* __restrict__ w, const float* __restrict__ bias, float* __restrict__ out)
{
    const float* hb = g_hb[0];
    const int b = blockIdx.y;
    const int o = blockIdx.x * 8 + (threadIdx.x >> 5);
    const int lane = threadIdx.x & 31;
    float acc = 0.f;
    const float* wr = w + (size_t)o * HH;
#pragma unroll 4
    for (int k = lane; k < HH; k += 32)
        acc = fmaf(hb[k * BB + b], wr[k], acc);
#pragma unroll
    for (int off = 16; off; off >>= 1) acc += __shfl_xor_sync(0xffffffffu, acc, off);
    if (lane == 0) out[b * OO + o] = acc + bias[o];
}

__global__ void reset_kernel() {
    if (threadIdx.x < 12) g_ctr[threadIdx.x] = 0;
}

extern "C" void kernel_launch(void* const* d_in, const int* in_sizes, int n_in,
                              void* d_out, int out_size)
{
    (void)in_sizes; (void)n_in; (void)out_size;
    const float* x     = (const float*)d_in[0];
    const float* lw_ih = (const float*)d_in[1];
    const float* lw_hh = (const float*)d_in[2];
    const float* lb_ih = (const float*)d_in[3];
    const float* lb_hh = (const float*)d_in[4];
    const float* l1g   = (const float*)d_in[5];
    const float* l1b   = (const float*)d_in[6];
    const float* gw_ih = (const float*)d_in[7];
    const float* gw_hh = (const float*)d_in[8];
    const float* gb_ih = (const float*)d_in[9];
    const float* gb_hh = (const float*)d_in[10];
    const float* l2g   = (const float*)d_in[11];
    const float* l2b   = (const float*)d_in[12];
    const float* rw_ih = (const float*)d_in[13];
    const float* rw_hh = (const float*)d_in[14];
    const float* rb_ih = (const float*)d_in[15];
    const float* rb_hh = (const float*)d_in[16];
    const float* fc_w  = (const float*)d_in[17];
    const float* fc_b  = (const float*)d_in[18];
    float* out = (float*)d_out;

    float *xg, *h1, *h2;
    cudaGetSymbolAddress((void**)&xg, g_xg);
    cudaGetSymbolAddress((void**)&h1, g_h1);
    cudaGetSymbolAddress((void**)&h2, g_h2);

    const int smem_lstm = (HH * BB + 32 * BB) * 4 + 8 * 256 * 16;
    const int smem_gru  = (HH * BB + 24 * BB) * 4 + 8 * 256 * 16;
    const int smem_rnn  = (HH * BB +  8 * BB) * 4 + 8 * 64 * 16;
    static int configured = 0;
    if (!configured) {
        cudaFuncSetAttribute(lstm_kernel, cudaFuncAttributeMaxDynamicSharedMemorySize, smem_lstm);
        cudaFuncSetAttribute(gru_kernel,  cudaFuncAttributeMaxDynamicSharedMemorySize, smem_gru);
        cudaFuncSetAttribute(rnn_kernel,  cudaFuncAttributeMaxDynamicSharedMemorySize, smem_rnn);
        configured = 1;
    }

    reset_kernel<<<1, 32>>>();

    const int M = BB * TT;
    gemm_kernel<1><<<dim3(4 * HH / 64, M / 128), 256>>>(x, lw_ih, lb_ih, lb_hh, xg, M, 4 * HH, II);
    lstm_kernel<<<NBLK, RT, smem_lstm>>>(xg, lw_hh, h1);
    ln_kernel<<<M, 128>>>(h1, l1g, l1b);

    gemm_kernel<2><<<dim3(3 * HH / 64, M / 128), 256>>>(h1, gw_ih, gb_ih, nullptr, xg, M, 3 * HH, HH);
    gru_kernel<<<NBLK, RT, smem_gru>>>(xg, gw_hh, gb_hh, h2);
    ln_kernel<<<M, 128>>>(h2, l2g, l2b);

    gemm_kernel<2><<<dim3(HH / 64, M / 128), 256>>>(h2, rw_ih, rb_ih, rb_hh, xg, M, HH, HH);
    rnn_kernel<<<NBLK, RT, smem_rnn>>>(xg, rw_hh);

    fc_kernel<<<dim3(OO / 8, BB), 256>>>(fc_w, fc_b, out);
}